// round 5
// baseline (speedup 1.0000x reference)
#include <cuda_runtime.h>
#include <math.h>

#define FULL 0xffffffffu

// ---------------------------------------------------------------------------
// Closed form (verified rounds 1-4): fold the trailing CNOT ring into the
// PauliZ masks; the measured state is a product state, so
//   <Z_w> = prod_{q in M_w} z_q,  M_w = {0..w} (w>=1), M_0 = {1..9}
//   RX-circuit: z = cos(h + theta) ; RY-circuit: z = cos(theta)*cos(h)
//
// Layout: 8 threads per row ("octet"), 4 rows/warp, 32 rows per 256-block,
// 512 blocks (131072 threads) for latency hiding.
//  - x loads issued BEFORE the W-staging __syncthreads (overlap DRAM latency).
//  - GEMM: thread accumulates 10 dots over its 16-column eighth; octet
//    xor-reduce (3 stages) gives every lane the full h vector.
//  - Both quads of an octet run the identical quad-wide epilogue (free:
//    lanes were idle); only the low quad (lane&4)==0 stores.
// ---------------------------------------------------------------------------
__global__ void __launch_bounds__(256)
qlstm_kernel(const float* __restrict__ x, const float* __restrict__ W,
             const float* __restrict__ b,
             const float* __restrict__ wf, const float* __restrict__ wi,
             const float* __restrict__ wu, const float* __restrict__ wo,
             float* __restrict__ out) {
    __shared__ float4 Ws[320];                 // W[o][f4]: [o*32 + f]
    __shared__ float2 s_f[10], s_u[10], s_o[10];
    __shared__ float  s_i[10];

    const int tid = threadIdx.x;
    const int oc  = tid & 7;                   // eighth within row
    const int row = (blockIdx.x * 256 + tid) >> 3;

    // ---- issue x loads first (hide DRAM latency behind setup) ----
    const float4* x4 = reinterpret_cast<const float4*>(x) + (size_t)row * 32;
    float4 xv[4];
#pragma unroll
    for (int i = 0; i < 4; i++) xv[i] = x4[i * 8 + oc];

    // ---- per-block setup: W -> smem, accurate sincos of weight angles ----
#pragma unroll
    for (int idx = tid; idx < 320; idx += 256)
        Ws[idx] = reinterpret_cast<const float4*>(W)[idx];
    if (tid < 40) {
        const int g = tid / 10, w = tid % 10;
        const float* p = (g == 0) ? wf : (g == 1) ? wi : (g == 2) ? wu : wo;
        float s, c;
        sincosf(p[w], &s, &c);
        if (g == 0)      s_f[w] = make_float2(c, s);
        else if (g == 1) s_i[w] = c;
        else if (g == 2) s_u[w] = make_float2(c, s);
        else             s_o[w] = make_float2(c, s);
    }
    __syncthreads();

    // ---- GEMM: h = x[row] @ W^T (16 cols per thread) ----
    float acc[10];
#pragma unroll
    for (int o = 0; o < 10; o++) acc[o] = 0.0f;
#pragma unroll
    for (int i = 0; i < 4; i++) {
#pragma unroll
        for (int o = 0; o < 10; o++) {
            const float4 wv = Ws[o * 32 + i * 8 + oc];
            acc[o] = fmaf(xv[i].x, wv.x,
                     fmaf(xv[i].y, wv.y,
                     fmaf(xv[i].z, wv.z,
                     fmaf(xv[i].w, wv.w, acc[o]))));
        }
    }
    // octet reduction: all 8 lanes end with the full sums
#pragma unroll
    for (int o = 0; o < 10; o++) {
        acc[o] += __shfl_xor_sync(FULL, acc[o], 1);
        acc[o] += __shfl_xor_sync(FULL, acc[o], 2);
        acc[o] += __shfl_xor_sync(FULL, acc[o], 4);
    }

    // ---- quad-wide epilogue (both quads of the octet run it identically) --
    const int lane = tid & 31;
    const int q = lane & 3;
    const int nw = (q < 3) ? 3 : 1;
    const int w0 = 3 * q;

    float myh[3], zf[3], zi[3], zu[3], zo[3];
#pragma unroll
    for (int j = 0; j < 3; j++) {
        float hv = acc[j];
        if (q == 1) hv = acc[3 + j];
        if (q == 2) hv = acc[6 + j];
        if (q == 3) hv = (j == 0) ? acc[9] : 0.0f;

        if (j < nw) {
            const int w = w0 + j;
            const float h = hv + __ldg(b + w);
            myh[j] = h;
            float sh, ch;
            __sincosf(h, &sh, &ch);
            const float2 cf = s_f[w], cu = s_u[w], co = s_o[w];
            zf[j] = ch * cf.x - sh * cf.y;     // RX: cos(h + wf)
            zi[j] = s_i[w] * ch;               // RY: cos(wi) * cos(h)
            zu[j] = ch * cu.x - sh * cu.y;
            zo[j] = ch * co.x - sh * co.y;
        } else {
            myh[j] = 0.0f;
            zf[j] = zi[j] = zu[j] = zo[j] = 1.0f;
        }
    }

    // per-circuit quad prefix products -> E[3] per circuit
    float Ef[3], Ei[3], Eu[3], Eo[3];
#pragma unroll
    for (int c = 0; c < 4; c++) {
        const float* z = (c == 0) ? zf : (c == 1) ? zi : (c == 2) ? zu : zo;
        const float l1 = z[0], l2 = l1 * z[1], l3 = l2 * z[2];

        float v = l3, t;
        t = __shfl_up_sync(FULL, v, 1, 4); if (q >= 1) v *= t;
        t = __shfl_up_sync(FULL, v, 2, 4); if (q >= 2) v *= t;
        float C = __shfl_up_sync(FULL, v, 1, 4); if (q == 0) C = 1.0f;

        float s = l3;
        t = __shfl_down_sync(FULL, s, 1, 4); if (q <= 2) s *= t;
        t = __shfl_down_sync(FULL, s, 2, 4); if (q <= 1) s *= t;
        const float R0 = __shfl_sync(FULL, s, 1, 4);

        float E0 = C * l1;
        if (q == 0) E0 = z[1] * z[2] * R0;              // wire 0: z1..z9
        const float E1 = C * l2, E2 = C * l3;

        if (c == 0)      { Ef[0] = E0; Ef[1] = E1; Ef[2] = E2; }
        else if (c == 1) { Ei[0] = E0; Ei[1] = E1; Ei[2] = E2; }
        else if (c == 2) { Eu[0] = E0; Eu[1] = E1; Eu[2] = E2; }
        else             { Eo[0] = E0; Eo[1] = E1; Eo[2] = E2; }
    }

    // ---- LSTM epilogue; only the low quad of each octet stores ----
    const bool writer = (lane & 4) == 0;
#pragma unroll
    for (int j = 0; j < 3; j++) {
        if (j < nw && writer) {
            const float ing = __fdividef(1.0f, 1.0f + __expf(-Ef[j]));
            const float fg  = __fdividef(1.0f, 1.0f + __expf(-Ei[j]));
            const float cg  = __fdividef(2.0f, 1.0f + __expf(-2.0f * Eu[j])) - 1.0f;
            const float og  = __fdividef(1.0f, 1.0f + __expf(-Eo[j]));
            const float nh  = fmaf(myh[j], fg, ing * cg);
            const float th  = __fdividef(2.0f, 1.0f + __expf(-2.0f * nh)) - 1.0f;
            out[row * 10 + w0 + j] = og * th;
        }
    }
}

extern "C" void kernel_launch(void* const* d_in, const int* in_sizes, int n_in,
                              void* d_out, int out_size) {
    const float* x  = (const float*)d_in[0];
    const float* W  = (const float*)d_in[1];
    const float* b  = (const float*)d_in[2];
    const float* wf = (const float*)d_in[3];
    const float* wi = (const float*)d_in[4];
    const float* wu = (const float*)d_in[5];
    const float* wo = (const float*)d_in[6];
    float* out = (float*)d_out;

    // 16384 rows x 8 threads = 131072 threads; 256/block -> 512 blocks
    qlstm_kernel<<<512, 256>>>(x, W, b, wf, wi, wu, wo, out);
}

// round 6
// speedup vs baseline: 1.0781x; 1.0781x over previous
#include <cuda_runtime.h>
#include <math.h>

#define FULL 0xffffffffu

// ---------------------------------------------------------------------------
// Closed form (verified rounds 1-5): fold the trailing CNOT ring into the
// PauliZ masks; the measured state is a product state, so
//   <Z_w> = prod_{q in M_w} z_q,  M_w = {0..w} (w>=1), M_0 = {1..9}
//   RX-circuit: z = cos(h + theta) ; RY-circuit: z = cos(theta)*cos(h)
//
// Layout: 8 threads/row ("octet"), 4 rows/warp, 128-thr blocks, 1024 blocks.
// NO shared memory, NO __syncthreads: W is read through __ldg (L1-resident,
// coalescer dedups the 4-lane-duplicate pattern), weight trig is computed
// inline per thread. Warps are fully independent -> the CTA scheduler
// backfills continuously and DRAM load bursts overlap other blocks' compute.
// ---------------------------------------------------------------------------
__global__ void __launch_bounds__(128)
qlstm_kernel(const float* __restrict__ x, const float* __restrict__ W,
             const float* __restrict__ b,
             const float* __restrict__ wf, const float* __restrict__ wi,
             const float* __restrict__ wu, const float* __restrict__ wo,
             float* __restrict__ out) {
    const int tid = threadIdx.x;
    const int oc  = tid & 7;                   // eighth within row
    const int row = (blockIdx.x * 128 + tid) >> 3;

    // ---- x loads first: streaming hint (read-once), deep front batch ----
    const float4* x4 = reinterpret_cast<const float4*>(x) + (size_t)row * 32;
    float4 xv[4];
#pragma unroll
    for (int i = 0; i < 4; i++) xv[i] = __ldcs(&x4[i * 8 + oc]);

    // ---- GEMM: h = x[row] @ W^T (16 cols per thread), W via L1 ----
    const float4* W4 = reinterpret_cast<const float4*>(W);
    float acc[10];
#pragma unroll
    for (int o = 0; o < 10; o++) acc[o] = 0.0f;
#pragma unroll
    for (int i = 0; i < 4; i++) {
#pragma unroll
        for (int o = 0; o < 10; o++) {
            const float4 wv = __ldg(&W4[o * 32 + i * 8 + oc]);
            acc[o] = fmaf(xv[i].x, wv.x,
                     fmaf(xv[i].y, wv.y,
                     fmaf(xv[i].z, wv.z,
                     fmaf(xv[i].w, wv.w, acc[o]))));
        }
    }
    // octet reduction: all 8 lanes end with the full sums
#pragma unroll
    for (int o = 0; o < 10; o++) {
        acc[o] += __shfl_xor_sync(FULL, acc[o], 1);
        acc[o] += __shfl_xor_sync(FULL, acc[o], 2);
        acc[o] += __shfl_xor_sync(FULL, acc[o], 4);
    }

    // ---- quad-wide epilogue (both quads of the octet run it identically) --
    const int lane = tid & 31;
    const int q = lane & 3;
    const int nw = (q < 3) ? 3 : 1;
    const int w0 = 3 * q;

    float myh[3], zf[3], zi[3], zu[3], zo[3];
#pragma unroll
    for (int j = 0; j < 3; j++) {
        float hv = acc[j];
        if (q == 1) hv = acc[3 + j];
        if (q == 2) hv = acc[6 + j];
        if (q == 3) hv = (j == 0) ? acc[9] : 0.0f;

        if (j < nw) {
            const int w = w0 + j;
            const float h = hv + __ldg(b + w);
            myh[j] = h;
            float sh, ch;
            __sincosf(h, &sh, &ch);
            float sf_, cf_, su_, cu_, so_, co_;
            __sincosf(__ldg(wf + w), &sf_, &cf_);
            __sincosf(__ldg(wu + w), &su_, &cu_);
            __sincosf(__ldg(wo + w), &so_, &co_);
            zf[j] = ch * cf_ - sh * sf_;       // RX: cos(h + wf)
            zi[j] = __cosf(__ldg(wi + w)) * ch; // RY: cos(wi) * cos(h)
            zu[j] = ch * cu_ - sh * su_;
            zo[j] = ch * co_ - sh * so_;
        } else {
            myh[j] = 0.0f;
            zf[j] = zi[j] = zu[j] = zo[j] = 1.0f;
        }
    }

    // per-circuit quad prefix products -> E[3] per circuit
    float Ef[3], Ei[3], Eu[3], Eo[3];
#pragma unroll
    for (int c = 0; c < 4; c++) {
        const float* z = (c == 0) ? zf : (c == 1) ? zi : (c == 2) ? zu : zo;
        const float l1 = z[0], l2 = l1 * z[1], l3 = l2 * z[2];

        float v = l3, t;
        t = __shfl_up_sync(FULL, v, 1, 4); if (q >= 1) v *= t;
        t = __shfl_up_sync(FULL, v, 2, 4); if (q >= 2) v *= t;
        float C = __shfl_up_sync(FULL, v, 1, 4); if (q == 0) C = 1.0f;

        float s = l3;
        t = __shfl_down_sync(FULL, s, 1, 4); if (q <= 2) s *= t;
        t = __shfl_down_sync(FULL, s, 2, 4); if (q <= 1) s *= t;
        const float R0 = __shfl_sync(FULL, s, 1, 4);

        float E0 = C * l1;
        if (q == 0) E0 = z[1] * z[2] * R0;              // wire 0: z1..z9
        const float E1 = C * l2, E2 = C * l3;

        if (c == 0)      { Ef[0] = E0; Ef[1] = E1; Ef[2] = E2; }
        else if (c == 1) { Ei[0] = E0; Ei[1] = E1; Ei[2] = E2; }
        else if (c == 2) { Eu[0] = E0; Eu[1] = E1; Eu[2] = E2; }
        else             { Eo[0] = E0; Eo[1] = E1; Eo[2] = E2; }
    }

    // ---- LSTM epilogue; only the low quad of each octet stores ----
    const bool writer = (lane & 4) == 0;
#pragma unroll
    for (int j = 0; j < 3; j++) {
        if (j < nw && writer) {
            const float ing = __fdividef(1.0f, 1.0f + __expf(-Ef[j]));
            const float fg  = __fdividef(1.0f, 1.0f + __expf(-Ei[j]));
            const float cg  = __fdividef(2.0f, 1.0f + __expf(-2.0f * Eu[j])) - 1.0f;
            const float og  = __fdividef(1.0f, 1.0f + __expf(-Eo[j]));
            const float nh  = fmaf(myh[j], fg, ing * cg);
            const float th  = __fdividef(2.0f, 1.0f + __expf(-2.0f * nh)) - 1.0f;
            out[row * 10 + w0 + j] = og * th;
        }
    }
}

extern "C" void kernel_launch(void* const* d_in, const int* in_sizes, int n_in,
                              void* d_out, int out_size) {
    const float* x  = (const float*)d_in[0];
    const float* W  = (const float*)d_in[1];
    const float* b  = (const float*)d_in[2];
    const float* wf = (const float*)d_in[3];
    const float* wi = (const float*)d_in[4];
    const float* wu = (const float*)d_in[5];
    const float* wo = (const float*)d_in[6];
    float* out = (float*)d_out;

    // 16384 rows x 8 threads = 131072 threads; 128/block -> 1024 blocks
    qlstm_kernel<<<1024, 128>>>(x, W, b, wf, wi, wu, wo, out);
}